// round 2
// baseline (speedup 1.0000x reference)
#include <cuda_runtime.h>
#include <math.h>

// Problem constants
#define BB   2
#define SS   256
#define INP  80
#define HID  128
#define F2   256
#define G4   512   // 4*HID
#define NCC  40
#define WSEG 64

// ---------------- device scratch (no allocation allowed) ----------------
__device__ float g_WihT0[2][INP][G4];    // [dir][i][g]
__device__ float g_WihT1[2][F2][G4];
__device__ float g_WhhT[2][2][HID][G4];  // [layer][dir][k][g]
__device__ float g_pre[2][BB][SS][G4];   // [dir][b][s][g]  (reused per layer)
__device__ float g_rnn[2][BB][SS][F2];   // [layer][b][s][f]
__device__ float g_cum[BB][SS][F2];
__device__ float g_WcT[F2][128];         // w_s1 c-part transposed, o padded 100->128 (zeros)
__device__ float g_WdT[F2][128];
__device__ float g_WeT[F2][128];
__device__ float g_wc1T[F2][80];
__device__ float g_wb1T[F2][80];
__device__ float g_dterm[BB][SS][128];   // prelu(rnn_i)@Wd^T + b_s1 (padded)
__device__ float g_eterm[BB][SS][128];   // prelu(rnn_j)@We^T
__device__ float g_scores[BB][SS][SS];   // scores[b][i][j], c = cum_j - cum_i
__device__ int   g_backptr[BB][SS];

__device__ __forceinline__ float sigf(float x) { return 1.0f / (1.0f + expf(-x)); }
__device__ __forceinline__ float preluf(float x, float a) { return x >= 0.0f ? x : a * x; }

// ---------------- prep: transpose weights into friendly layouts ----------------
__global__ void prep_k(const float* __restrict__ wih0f, const float* __restrict__ whh0f,
                       const float* __restrict__ wih0b, const float* __restrict__ whh0b,
                       const float* __restrict__ wih1f, const float* __restrict__ whh1f,
                       const float* __restrict__ wih1b, const float* __restrict__ whh1b,
                       const float* __restrict__ ws1,  const float* __restrict__ wc1,
                       const float* __restrict__ wb1)
{
    int idx = blockIdx.x * blockDim.x + threadIdx.x;
    int n = gridDim.x * blockDim.x;
    for (int p = idx; p < 2 * INP * G4; p += n) {
        int d = p / (INP * G4), r = p % (INP * G4), i = r / G4, g = r % G4;
        g_WihT0[d][i][g] = (d ? wih0b : wih0f)[g * INP + i];
    }
    for (int p = idx; p < 2 * F2 * G4; p += n) {
        int d = p / (F2 * G4), r = p % (F2 * G4), i = r / G4, g = r % G4;
        g_WihT1[d][i][g] = (d ? wih1b : wih1f)[g * F2 + i];
    }
    for (int p = idx; p < 2 * 2 * HID * G4; p += n) {
        int l = p / (2 * HID * G4), r = p % (2 * HID * G4);
        int d = r / (HID * G4), r2 = r % (HID * G4), k = r2 / G4, g = r2 % G4;
        const float* w = l ? (d ? whh1b : whh1f) : (d ? whh0b : whh0f);
        g_WhhT[l][d][k][g] = w[g * HID + k];
    }
    for (int p = idx; p < F2 * 128; p += n) {
        int k = p / 128, o = p % 128;
        g_WcT[k][o] = (o < 100) ? ws1[o * 768 + k]        : 0.0f;
        g_WdT[k][o] = (o < 100) ? ws1[o * 768 + 256 + k]  : 0.0f;
        g_WeT[k][o] = (o < 100) ? ws1[o * 768 + 512 + k]  : 0.0f;
    }
    for (int p = idx; p < F2 * 80; p += n) {
        int k = p / 80, o = p % 80;
        g_wc1T[k][o] = wc1[o * F2 + k];
        g_wb1T[k][o] = wb1[o * F2 + k];
    }
}

// ---------------- input projection: pre = x @ Wih^T + b ----------------
template <int INDIM>
__global__ void inproj_k(const float* __restrict__ x0,
                         const float* __restrict__ bias_f, const float* __restrict__ bias_b,
                         int layer)
{
    int st = blockIdx.x * 8, b = blockIdx.y, d = blockIdx.z, g = threadIdx.x; // 512 threads
    __shared__ float xs[8][INDIM];
    const float* xin = layer ? &g_rnn[0][0][0][0] : x0;
    for (int p = g; p < 8 * INDIM; p += 512) {
        int ss = p / INDIM, i = p % INDIM;
        xs[ss][i] = xin[(b * SS + st + ss) * INDIM + i];
    }
    __syncthreads();
    const float* W = (INDIM == INP) ? &g_WihT0[d][0][0] : &g_WihT1[d][0][0];
    float bg = (d ? bias_b : bias_f)[g];
    float acc[8];
#pragma unroll
    for (int ss = 0; ss < 8; ss++) acc[ss] = bg;
    for (int i = 0; i < INDIM; i++) {
        float w = W[i * G4 + g];
#pragma unroll
        for (int ss = 0; ss < 8; ss++) acc[ss] = fmaf(xs[ss][i], w, acc[ss]);
    }
#pragma unroll
    for (int ss = 0; ss < 8; ss++) g_pre[d][b][st + ss][g] = acc[ss];
}

// ---------------- LSTM recurrence: one CTA per (b, dir) ----------------
__global__ void recur_k(int layer)
{
    int b = blockIdx.x, d = blockIdx.y, t = threadIdx.x; // 128 threads, 4 gates each
    __shared__ float h_sh[HID];
    __shared__ float gs[G4];
    float c = 0.0f;
    h_sh[t] = 0.0f;
    __syncthreads();
    const float4* W4 = reinterpret_cast<const float4*>(&g_WhhT[layer][d][0][0]);
    const float* preB = &g_pre[d][b][0][0];
    float* out = &g_rnn[layer][b][0][0];
    for (int step = 0; step < SS; ++step) {
        int s = d ? (SS - 1 - step) : step;
        float4 p = reinterpret_cast<const float4*>(preB + s * G4)[t];
        float a0 = p.x, a1 = p.y, a2 = p.z, a3 = p.w;
#pragma unroll 8
        for (int k = 0; k < HID; k++) {
            float h = h_sh[k];
            float4 w = W4[k * 128 + t];
            a0 = fmaf(h, w.x, a0); a1 = fmaf(h, w.y, a1);
            a2 = fmaf(h, w.z, a2); a3 = fmaf(h, w.w, a3);
        }
        reinterpret_cast<float4*>(gs)[t] = make_float4(a0, a1, a2, a3);
        __syncthreads();
        float gi = gs[t], gf = gs[HID + t], gg = gs[2 * HID + t], go = gs[3 * HID + t];
        c = sigf(gf) * c + sigf(gi) * tanhf(gg);
        float h = sigf(go) * tanhf(c);
        h_sh[t] = h;
        out[s * F2 + d * HID + t] = h;
        __syncthreads();
    }
}

// ---------------- cumsum over time ----------------
__global__ void cumsum_k()
{
    int b = blockIdx.x, k = threadIdx.x; // 256
    float run = 0.0f;
    for (int s = 0; s < SS; s++) {
        run += g_rnn[1][b][s][k];
        g_cum[b][s][k] = run;
    }
}

// ---------------- dterm/eterm precompute ----------------
__global__ void determ_k(const float* __restrict__ a_s0p, const float* __restrict__ bs1)
{
    int s = blockIdx.x, b = blockIdx.y, t = threadIdx.x; // 128
    __shared__ float pr[F2];
    float a0 = *a_s0p;
    for (int p = t; p < F2; p += 128) pr[p] = preluf(g_rnn[1][b][s][p], a0);
    __syncthreads();
    float ad = 0.0f, ae = 0.0f;
    for (int k = 0; k < F2; k++) {
        float p = pr[k];
        ad = fmaf(p, g_WdT[k][t], ad);
        ae = fmaf(p, g_WeT[k][t], ae);
    }
    g_dterm[b][s][t] = ad + ((t < 100) ? bs1[t] : 0.0f);
    g_eterm[b][s][t] = ae;
}

// ---------------- cls / bin MLPs ----------------
__global__ void clsbin_k(const float* __restrict__ ac0, const float* __restrict__ bc1,
                         const float* __restrict__ ac1, const float* __restrict__ wc2,
                         const float* __restrict__ bc2,
                         const float* __restrict__ ab0, const float* __restrict__ bb1,
                         const float* __restrict__ ab1, const float* __restrict__ wb2,
                         const float* __restrict__ bb2, float* __restrict__ out)
{
    int s = blockIdx.x, b = blockIdx.y, t = threadIdx.x; // 128
    __shared__ float pr[F2];
    __shared__ float h1[80];
    // CLS
    float a = *ac0;
    for (int p = t; p < F2; p += 128) pr[p] = preluf(g_rnn[1][b][s][p], a);
    __syncthreads();
    if (t < 80) {
        float acc = bc1[t];
        for (int k = 0; k < F2; k++) acc = fmaf(pr[k], g_wc1T[k][t], acc);
        h1[t] = preluf(acc, *ac1);
    }
    __syncthreads();
    if (t < NCC) {
        float acc = bc2[t];
        for (int q = 0; q < 80; q++) acc = fmaf(h1[q], wc2[t * 80 + q], acc);
        out[(b * SS + s) * NCC + t] = acc;
    }
    __syncthreads();
    // BIN
    a = *ab0;
    for (int p = t; p < F2; p += 128) pr[p] = preluf(g_rnn[1][b][s][p], a);
    __syncthreads();
    if (t < 80) {
        float acc = bb1[t];
        for (int k = 0; k < F2; k++) acc = fmaf(pr[k], g_wb1T[k][t], acc);
        h1[t] = preluf(acc, *ab1);
    }
    __syncthreads();
    if (t < 2) {
        float acc = bb2[t];
        for (int q = 0; q < 80; q++) acc = fmaf(h1[q], wb2[t * 80 + q], acc);
        out[20480 + (b * SS + s) * 2 + t] = acc;
    }
}

// ---------------- pairwise scores: block = (i, b), 256 threads ----------------
__global__ void scores_k(const float* __restrict__ a_s0p, const float* __restrict__ a_s1p,
                         const float* __restrict__ ws2, const float* __restrict__ bs2)
{
    int i = blockIdx.x, b = blockIdx.y, tid = threadIdx.x;
    int jj = tid >> 4, oq = tid & 15;           // 16 j's per tile x 16 output-groups
    __shared__ float cum_i[F2];
    __shared__ float T[16][257];
    float a0 = *a_s0p, a1 = *a_s1p;
    for (int p = tid; p < F2; p += 256) cum_i[p] = g_cum[b][i][p];
    float dt[8], w2[8];
#pragma unroll
    for (int r = 0; r < 8; r++) {
        int o = oq * 8 + r;
        dt[r] = g_dterm[b][i][o];
        w2[r] = (o < 100) ? ws2[o] : 0.0f;
    }
    float bs2v = bs2[0];
    __syncthreads();
    const float4* W4 = reinterpret_cast<const float4*>(&g_WcT[0][0]);
    for (int jt = 0; jt < 16; jt++) {
        int j0 = jt * 16;
        for (int p = tid; p < 16 * F2; p += 256) {
            int lj = p >> 8, k = p & 255;
            float v = g_cum[b][j0 + lj][k] - cum_i[k];
            T[lj][k] = preluf(v, a0);
        }
        __syncthreads();
        float acc[8] = {0, 0, 0, 0, 0, 0, 0, 0};
#pragma unroll 4
        for (int k = 0; k < F2; k++) {
            float tv = T[jj][k];
            float4 wA = W4[k * 32 + oq * 2];
            float4 wB = W4[k * 32 + oq * 2 + 1];
            acc[0] = fmaf(tv, wA.x, acc[0]); acc[1] = fmaf(tv, wA.y, acc[1]);
            acc[2] = fmaf(tv, wA.z, acc[2]); acc[3] = fmaf(tv, wA.w, acc[3]);
            acc[4] = fmaf(tv, wB.x, acc[4]); acc[5] = fmaf(tv, wB.y, acc[5]);
            acc[6] = fmaf(tv, wB.z, acc[6]); acc[7] = fmaf(tv, wB.w, acc[7]);
        }
        int j = j0 + jj;
        float part = 0.0f;
#pragma unroll
        for (int r = 0; r < 8; r++) {
            int o = oq * 8 + r;
            float h = acc[r] + dt[r] + g_eterm[b][j][o];
            h = preluf(h, a1);
            part = fmaf(h, w2[r], part);
        }
#pragma unroll
        for (int off = 8; off > 0; off >>= 1)
            part += __shfl_down_sync(0xffffffffu, part, off, 16);
        if (oq == 0) g_scores[b][i][j] = part + bs2v;
        __syncthreads();
    }
}

// ---------------- DP backpointers ----------------
__global__ void dp_k()
{
    int b = blockIdx.x, t = threadIdx.x; // 64 threads
    __shared__ float best[SS];
    __shared__ float rv[2];
    __shared__ int ri[2];
    for (int p = t; p < SS; p += 64) best[p] = 0.0f;
    if (t == 0) g_backptr[b][0] = 0;
    __syncthreads();
    for (int i = 1; i < SS; i++) {
        int start = (i > WSEG) ? (i - WSEG) : 0;
        int j = start + t;
        float v = (j < i) ? best[j] + g_scores[b][j][i] : -1000000000.0f;
        int idx = j;
#pragma unroll
        for (int off = 16; off > 0; off >>= 1) {
            float ov = __shfl_down_sync(0xffffffffu, v, off);
            int oi = __shfl_down_sync(0xffffffffu, idx, off);
            if (ov > v || (ov == v && oi < idx)) { v = ov; idx = oi; }
        }
        if ((t & 31) == 0) { rv[t >> 5] = v; ri[t >> 5] = idx; }
        __syncthreads();
        if (t == 0) {
            float v0 = rv[0], v1 = rv[1];
            int i0 = ri[0], i1 = ri[1];
            if (v1 > v0 || (v1 == v0 && i1 < i0)) { v0 = v1; i0 = i1; }
            best[i] = v0;
            g_backptr[b][i] = i0;
        }
        __syncthreads();
    }
}

// ---------------- backtrack + output bmask/pred_scores ----------------
__global__ void backtrack_k(const int* __restrict__ lengths, float* __restrict__ out)
{
    int t = threadIdx.x; // 256
    for (int p = t; p < BB * SS; p += 256) out[21504 + p] = 0.0f;
    __syncthreads();
    if (t < BB) {
        int b = t;
        int cur = lengths[b] - 1;
        float acc = 0.0f;
        for (int it = 0; it < SS; it++) {
            out[21504 + b * SS + cur] = 1.0f;
            int prev = g_backptr[b][cur];
            if (cur > 0) {
                acc += g_scores[b][prev][cur];
                cur = prev;
            } else {
                cur = 0;
            }
        }
        out[22016 + b] = acc;
    }
}

// ---------------- launch ----------------
extern "C" void kernel_launch(void* const* d_in, const int* in_sizes, int n_in,
                              void* d_out, int out_size)
{
    const float* x       = (const float*)d_in[0];
    const int*   lengths = (const int*)d_in[1];
    const float* wih0f = (const float*)d_in[2];
    const float* whh0f = (const float*)d_in[3];
    const float* bl0f  = (const float*)d_in[4];
    const float* wih0b = (const float*)d_in[5];
    const float* whh0b = (const float*)d_in[6];
    const float* bl0b  = (const float*)d_in[7];
    const float* wih1f = (const float*)d_in[8];
    const float* whh1f = (const float*)d_in[9];
    const float* bl1f  = (const float*)d_in[10];
    const float* wih1b = (const float*)d_in[11];
    const float* whh1b = (const float*)d_in[12];
    const float* bl1b  = (const float*)d_in[13];
    const float* a_s0 = (const float*)d_in[14];
    const float* w_s1 = (const float*)d_in[15];
    const float* b_s1 = (const float*)d_in[16];
    const float* a_s1 = (const float*)d_in[17];
    const float* w_s2 = (const float*)d_in[18];
    const float* b_s2 = (const float*)d_in[19];
    const float* a_c0 = (const float*)d_in[20];
    const float* w_c1 = (const float*)d_in[21];
    const float* b_c1 = (const float*)d_in[22];
    const float* a_c1 = (const float*)d_in[23];
    const float* w_c2 = (const float*)d_in[24];
    const float* b_c2 = (const float*)d_in[25];
    const float* a_b0 = (const float*)d_in[26];
    const float* w_b1 = (const float*)d_in[27];
    const float* b_b1 = (const float*)d_in[28];
    const float* a_b1 = (const float*)d_in[29];
    const float* w_b2 = (const float*)d_in[30];
    const float* b_b2 = (const float*)d_in[31];
    float* out = (float*)d_out;

    prep_k<<<512, 256>>>(wih0f, whh0f, wih0b, whh0b, wih1f, whh1f, wih1b, whh1b,
                         w_s1, w_c1, w_b1);

    inproj_k<INP><<<dim3(SS / 8, BB, 2), 512>>>(x, bl0f, bl0b, 0);
    recur_k<<<dim3(BB, 2), HID>>>(0);
    inproj_k<F2><<<dim3(SS / 8, BB, 2), 512>>>(x, bl1f, bl1b, 1);
    recur_k<<<dim3(BB, 2), HID>>>(1);

    cumsum_k<<<BB, F2>>>();
    determ_k<<<dim3(SS, BB), 128>>>(a_s0, b_s1);
    clsbin_k<<<dim3(SS, BB), 128>>>(a_c0, b_c1, a_c1, w_c2, b_c2,
                                    a_b0, b_b1, a_b1, w_b2, b_b2, out);
    scores_k<<<dim3(SS, BB), 256>>>(a_s0, a_s1, w_s2, b_s2);
    dp_k<<<BB, 64>>>();
    backtrack_k<<<1, 256>>>(lengths, out);
}

// round 3
// speedup vs baseline: 2.0706x; 2.0706x over previous
#include <cuda_runtime.h>
#include <math.h>

// Problem constants
#define BB   2
#define SS   256
#define INP  80
#define HID  128
#define F2   256
#define G4   512   // 4*HID
#define NCC  40
#define WSEG 64

// ---------------- device scratch (no allocation allowed) ----------------
__device__ float g_WihT0[2][INP][G4];    // [dir][i][g]
__device__ float g_WihT1[2][F2][G4];
__device__ float g_WhhT[2][2][HID][G4];  // [layer][dir][k][g]
__device__ float g_pre[2][BB][SS][G4];   // [dir][b][s][g]  (reused per layer)
__device__ float g_rnn[2][BB][SS][F2];   // [layer][b][s][f]
__device__ float g_cum[BB][SS][F2];
__device__ float g_WcT[F2][128];         // w_s1 c-part transposed, o padded 100->128 (zeros)
__device__ float g_WdT[F2][128];
__device__ float g_WeT[F2][128];
__device__ float g_wc1T[F2][80];
__device__ float g_wb1T[F2][80];
__device__ float g_dterm[BB][SS][128];   // prelu(rnn_i)@Wd^T + b_s1 (padded)
__device__ float g_eterm[BB][SS][128];   // prelu(rnn_j)@We^T
__device__ float g_scores[BB][SS][SS];   // scores[b][i][j], c = cum_j - cum_i
__device__ int   g_backptr[BB][SS];

__device__ __forceinline__ float sigf(float x) { return 1.0f / (1.0f + expf(-x)); }
__device__ __forceinline__ float preluf(float x, float a) { return x >= 0.0f ? x : a * x; }

// ---------------- prep: transpose weights into friendly layouts ----------------
__global__ void prep_k(const float* __restrict__ wih0f, const float* __restrict__ whh0f,
                       const float* __restrict__ wih0b, const float* __restrict__ whh0b,
                       const float* __restrict__ wih1f, const float* __restrict__ whh1f,
                       const float* __restrict__ wih1b, const float* __restrict__ whh1b,
                       const float* __restrict__ ws1,  const float* __restrict__ wc1,
                       const float* __restrict__ wb1)
{
    int idx = blockIdx.x * blockDim.x + threadIdx.x;
    int n = gridDim.x * blockDim.x;
    for (int p = idx; p < 2 * INP * G4; p += n) {
        int d = p / (INP * G4), r = p % (INP * G4), i = r / G4, g = r % G4;
        g_WihT0[d][i][g] = (d ? wih0b : wih0f)[g * INP + i];
    }
    for (int p = idx; p < 2 * F2 * G4; p += n) {
        int d = p / (F2 * G4), r = p % (F2 * G4), i = r / G4, g = r % G4;
        g_WihT1[d][i][g] = (d ? wih1b : wih1f)[g * F2 + i];
    }
    for (int p = idx; p < 2 * 2 * HID * G4; p += n) {
        int l = p / (2 * HID * G4), r = p % (2 * HID * G4);
        int d = r / (HID * G4), r2 = r % (HID * G4), k = r2 / G4, g = r2 % G4;
        const float* w = l ? (d ? whh1b : whh1f) : (d ? whh0b : whh0f);
        g_WhhT[l][d][k][g] = w[g * HID + k];
    }
    for (int p = idx; p < F2 * 128; p += n) {
        int k = p / 128, o = p % 128;
        g_WcT[k][o] = (o < 100) ? ws1[o * 768 + k]        : 0.0f;
        g_WdT[k][o] = (o < 100) ? ws1[o * 768 + 256 + k]  : 0.0f;
        g_WeT[k][o] = (o < 100) ? ws1[o * 768 + 512 + k]  : 0.0f;
    }
    for (int p = idx; p < F2 * 80; p += n) {
        int k = p / 80, o = p % 80;
        g_wc1T[k][o] = wc1[o * F2 + k];
        g_wb1T[k][o] = wb1[o * F2 + k];
    }
}

// ---------------- input projection: pre = x @ Wih^T + b ----------------
template <int INDIM>
__global__ void inproj_k(const float* __restrict__ x0,
                         const float* __restrict__ bias_f, const float* __restrict__ bias_b,
                         int layer)
{
    int st = blockIdx.x * 8, b = blockIdx.y, d = blockIdx.z, g = threadIdx.x; // 512 threads
    __shared__ float xs[8][INDIM];
    const float* xin = layer ? &g_rnn[0][0][0][0] : x0;
    for (int p = g; p < 8 * INDIM; p += 512) {
        int ss = p / INDIM, i = p % INDIM;
        xs[ss][i] = xin[(b * SS + st + ss) * INDIM + i];
    }
    __syncthreads();
    const float* W = (INDIM == INP) ? &g_WihT0[d][0][0] : &g_WihT1[d][0][0];
    float bg = (d ? bias_b : bias_f)[g];
    float acc[8];
#pragma unroll
    for (int ss = 0; ss < 8; ss++) acc[ss] = bg;
    for (int i = 0; i < INDIM; i++) {
        float w = W[i * G4 + g];
#pragma unroll
        for (int ss = 0; ss < 8; ss++) acc[ss] = fmaf(xs[ss][i], w, acc[ss]);
    }
#pragma unroll
    for (int ss = 0; ss < 8; ss++) g_pre[d][b][st + ss][g] = acc[ss];
}

// ---------------- LSTM recurrence: one CTA per (b, dir), 256 threads ----------------
__global__ void __launch_bounds__(256) recur_k(int layer)
{
    int b = blockIdx.x, d = blockIdx.y, t = threadIdx.x; // 256 threads, 2 gate outputs each
    __shared__ float hs[HID];
    __shared__ float gs[G4];
    float c = 0.0f;
    if (t < HID) hs[t] = 0.0f;
    __syncthreads();
    const float2* __restrict__ W2 = reinterpret_cast<const float2*>(&g_WhhT[layer][d][0][0]); // [k][256] float2
    const float2* __restrict__ preB = reinterpret_cast<const float2*>(&g_pre[d][b][0][0]);
    float* out = &g_rnn[layer][b][0][0];
    const float4* hs4 = reinterpret_cast<const float4*>(hs);
    for (int step = 0; step < SS; ++step) {
        int s = d ? (SS - 1 - step) : step;
        float2 p = preB[s * 256 + t];
        float a0 = p.x, a1 = p.y;
#pragma unroll 8
        for (int k4 = 0; k4 < 32; k4++) {
            float4 h = hs4[k4];
            float2 w0 = W2[(k4 * 4 + 0) * 256 + t];
            float2 w1 = W2[(k4 * 4 + 1) * 256 + t];
            float2 w2 = W2[(k4 * 4 + 2) * 256 + t];
            float2 w3 = W2[(k4 * 4 + 3) * 256 + t];
            a0 = fmaf(h.x, w0.x, a0); a1 = fmaf(h.x, w0.y, a1);
            a0 = fmaf(h.y, w1.x, a0); a1 = fmaf(h.y, w1.y, a1);
            a0 = fmaf(h.z, w2.x, a0); a1 = fmaf(h.z, w2.y, a1);
            a0 = fmaf(h.w, w3.x, a0); a1 = fmaf(h.w, w3.y, a1);
        }
        gs[2 * t] = a0; gs[2 * t + 1] = a1;
        __syncthreads();
        if (t < HID) {
            float gi = gs[t], gf = gs[HID + t], gg = gs[2 * HID + t], go = gs[3 * HID + t];
            c = sigf(gf) * c + sigf(gi) * tanhf(gg);
            float h = sigf(go) * tanhf(c);
            hs[t] = h;
            out[s * F2 + d * HID + t] = h;
        }
        __syncthreads();
    }
}

// ---------------- cumsum over time ----------------
__global__ void cumsum_k()
{
    int b = blockIdx.x, k = threadIdx.x; // 256
    float run = 0.0f;
#pragma unroll 4
    for (int s = 0; s < SS; s++) {
        run += g_rnn[1][b][s][k];
        g_cum[b][s][k] = run;
    }
}

// ---------------- dterm/eterm precompute ----------------
__global__ void determ_k(const float* __restrict__ a_s0p, const float* __restrict__ bs1)
{
    int s = blockIdx.x, b = blockIdx.y, t = threadIdx.x; // 128
    __shared__ float pr[F2];
    float a0 = *a_s0p;
    for (int p = t; p < F2; p += 128) pr[p] = preluf(g_rnn[1][b][s][p], a0);
    __syncthreads();
    float ad = 0.0f, ae = 0.0f;
    for (int k = 0; k < F2; k++) {
        float p = pr[k];
        ad = fmaf(p, g_WdT[k][t], ad);
        ae = fmaf(p, g_WeT[k][t], ae);
    }
    g_dterm[b][s][t] = ad + ((t < 100) ? bs1[t] : 0.0f);
    g_eterm[b][s][t] = ae;
}

// ---------------- cls / bin MLPs ----------------
__global__ void clsbin_k(const float* __restrict__ ac0, const float* __restrict__ bc1,
                         const float* __restrict__ ac1, const float* __restrict__ wc2,
                         const float* __restrict__ bc2,
                         const float* __restrict__ ab0, const float* __restrict__ bb1,
                         const float* __restrict__ ab1, const float* __restrict__ wb2,
                         const float* __restrict__ bb2, float* __restrict__ out)
{
    int s = blockIdx.x, b = blockIdx.y, t = threadIdx.x; // 128
    __shared__ float pr[F2];
    __shared__ float h1[80];
    // CLS
    float a = *ac0;
    for (int p = t; p < F2; p += 128) pr[p] = preluf(g_rnn[1][b][s][p], a);
    __syncthreads();
    if (t < 80) {
        float acc = bc1[t];
        for (int k = 0; k < F2; k++) acc = fmaf(pr[k], g_wc1T[k][t], acc);
        h1[t] = preluf(acc, *ac1);
    }
    __syncthreads();
    if (t < NCC) {
        float acc = bc2[t];
        for (int q = 0; q < 80; q++) acc = fmaf(h1[q], wc2[t * 80 + q], acc);
        out[(b * SS + s) * NCC + t] = acc;
    }
    __syncthreads();
    // BIN
    a = *ab0;
    for (int p = t; p < F2; p += 128) pr[p] = preluf(g_rnn[1][b][s][p], a);
    __syncthreads();
    if (t < 80) {
        float acc = bb1[t];
        for (int k = 0; k < F2; k++) acc = fmaf(pr[k], g_wb1T[k][t], acc);
        h1[t] = preluf(acc, *ab1);
    }
    __syncthreads();
    if (t < 2) {
        float acc = bb2[t];
        for (int q = 0; q < 80; q++) acc = fmaf(h1[q], wb2[t * 80 + q], acc);
        out[20480 + (b * SS + s) * 2 + t] = acc;
    }
}

// ---------------- pairwise scores: block = (i, b), 256 threads ----------------
// Register-blocked: each thread computes 4 j's x 8 outputs (32 accumulators).
// k split into two 128-halves so the 64-row T tile fits in static smem.
#define TROW 132   // 128 k-half + 4 pad (bank-shift 4/row)
__global__ void __launch_bounds__(256) scores_k(const float* __restrict__ a_s0p,
                         const float* __restrict__ a_s1p,
                         const float* __restrict__ ws2, const float* __restrict__ bs2)
{
    int i = blockIdx.x, b = blockIdx.y, tid = threadIdx.x;
    int oq = tid & 15, jg = tid >> 4;   // 16 output-groups x 16 j-groups(4 j)
    __shared__ float cum_i[F2];
    __shared__ float T[64 * TROW];
    float a0 = *a_s0p, a1 = *a_s1p;
    for (int p = tid; p < F2; p += 256) cum_i[p] = g_cum[b][i][p];
    float dt[8], w2v[8];
#pragma unroll
    for (int r = 0; r < 8; r++) {
        int o = oq * 8 + r;
        dt[r] = g_dterm[b][i][o];
        w2v[r] = (o < 100) ? ws2[o] : 0.0f;
    }
    float bs2v = bs2[0];
    __syncthreads();
    const float4* __restrict__ W4 = reinterpret_cast<const float4*>(&g_WcT[0][0]);
    for (int tile = 0; tile < 4; tile++) {
        int j0 = tile * 64;
        float acc[4][8];
#pragma unroll
        for (int r4 = 0; r4 < 4; r4++)
#pragma unroll
            for (int r = 0; r < 8; r++) acc[r4][r] = 0.0f;

        for (int kh = 0; kh < 2; kh++) {
            int kb = kh * 128;
            // fill T[64][128] for this k-half
            for (int p = tid; p < 64 * 128; p += 256) {
                int lj = p >> 7, k = p & 127;
                T[lj * TROW + k] = preluf(g_cum[b][j0 + lj][kb + k] - cum_i[kb + k], a0);
            }
            __syncthreads();
            const float* T0 = &T[(jg * 4 + 0) * TROW];
            const float* T1 = &T[(jg * 4 + 1) * TROW];
            const float* T2 = &T[(jg * 4 + 2) * TROW];
            const float* T3 = &T[(jg * 4 + 3) * TROW];
#pragma unroll 2
            for (int k = 0; k < 128; k++) {
                float4 wA = W4[(kb + k) * 32 + oq * 2];
                float4 wB = W4[(kb + k) * 32 + oq * 2 + 1];
                float t0 = T0[k], t1 = T1[k], t2 = T2[k], t3 = T3[k];
                acc[0][0] = fmaf(t0, wA.x, acc[0][0]); acc[0][1] = fmaf(t0, wA.y, acc[0][1]);
                acc[0][2] = fmaf(t0, wA.z, acc[0][2]); acc[0][3] = fmaf(t0, wA.w, acc[0][3]);
                acc[0][4] = fmaf(t0, wB.x, acc[0][4]); acc[0][5] = fmaf(t0, wB.y, acc[0][5]);
                acc[0][6] = fmaf(t0, wB.z, acc[0][6]); acc[0][7] = fmaf(t0, wB.w, acc[0][7]);
                acc[1][0] = fmaf(t1, wA.x, acc[1][0]); acc[1][1] = fmaf(t1, wA.y, acc[1][1]);
                acc[1][2] = fmaf(t1, wA.z, acc[1][2]); acc[1][3] = fmaf(t1, wA.w, acc[1][3]);
                acc[1][4] = fmaf(t1, wB.x, acc[1][4]); acc[1][5] = fmaf(t1, wB.y, acc[1][5]);
                acc[1][6] = fmaf(t1, wB.z, acc[1][6]); acc[1][7] = fmaf(t1, wB.w, acc[1][7]);
                acc[2][0] = fmaf(t2, wA.x, acc[2][0]); acc[2][1] = fmaf(t2, wA.y, acc[2][1]);
                acc[2][2] = fmaf(t2, wA.z, acc[2][2]); acc[2][3] = fmaf(t2, wA.w, acc[2][3]);
                acc[2][4] = fmaf(t2, wB.x, acc[2][4]); acc[2][5] = fmaf(t2, wB.y, acc[2][5]);
                acc[2][6] = fmaf(t2, wB.z, acc[2][6]); acc[2][7] = fmaf(t2, wB.w, acc[2][7]);
                acc[3][0] = fmaf(t3, wA.x, acc[3][0]); acc[3][1] = fmaf(t3, wA.y, acc[3][1]);
                acc[3][2] = fmaf(t3, wA.z, acc[3][2]); acc[3][3] = fmaf(t3, wA.w, acc[3][3]);
                acc[3][4] = fmaf(t3, wB.x, acc[3][4]); acc[3][5] = fmaf(t3, wB.y, acc[3][5]);
                acc[3][6] = fmaf(t3, wB.z, acc[3][6]); acc[3][7] = fmaf(t3, wB.w, acc[3][7]);
            }
            __syncthreads();
        }
        // epilogue: 4 j's per thread
#pragma unroll
        for (int r4 = 0; r4 < 4; r4++) {
            int j = j0 + jg * 4 + r4;
            float part = 0.0f;
#pragma unroll
            for (int r = 0; r < 8; r++) {
                int o = oq * 8 + r;
                float h = acc[r4][r] + dt[r] + g_eterm[b][j][o];
                h = preluf(h, a1);
                part = fmaf(h, w2v[r], part);
            }
#pragma unroll
            for (int off = 8; off > 0; off >>= 1)
                part += __shfl_down_sync(0xffffffffu, part, off, 16);
            if (oq == 0) g_scores[b][i][j] = part + bs2v;
        }
    }
}

// ---------------- DP backpointers ----------------
__global__ void dp_k()
{
    int b = blockIdx.x, t = threadIdx.x; // 64 threads
    __shared__ float best[SS];
    __shared__ float rv[2];
    __shared__ int ri[2];
    for (int p = t; p < SS; p += 64) best[p] = 0.0f;
    if (t == 0) g_backptr[b][0] = 0;
    __syncthreads();
    for (int i = 1; i < SS; i++) {
        int start = (i > WSEG) ? (i - WSEG) : 0;
        int j = start + t;
        float v = (j < i) ? best[j] + g_scores[b][j][i] : -1000000000.0f;
        int idx = j;
#pragma unroll
        for (int off = 16; off > 0; off >>= 1) {
            float ov = __shfl_down_sync(0xffffffffu, v, off);
            int oi = __shfl_down_sync(0xffffffffu, idx, off);
            if (ov > v || (ov == v && oi < idx)) { v = ov; idx = oi; }
        }
        if ((t & 31) == 0) { rv[t >> 5] = v; ri[t >> 5] = idx; }
        __syncthreads();
        if (t == 0) {
            float v0 = rv[0], v1 = rv[1];
            int i0 = ri[0], i1 = ri[1];
            if (v1 > v0 || (v1 == v0 && i1 < i0)) { v0 = v1; i0 = i1; }
            best[i] = v0;
            g_backptr[b][i] = i0;
        }
        __syncthreads();
    }
}

// ---------------- backtrack + output bmask/pred_scores ----------------
__global__ void backtrack_k(const int* __restrict__ lengths, float* __restrict__ out)
{
    int t = threadIdx.x; // 256
    for (int p = t; p < BB * SS; p += 256) out[21504 + p] = 0.0f;
    __syncthreads();
    if (t < BB) {
        int b = t;
        int cur = lengths[b] - 1;
        float acc = 0.0f;
        for (int it = 0; it < SS; it++) {
            out[21504 + b * SS + cur] = 1.0f;
            int prev = g_backptr[b][cur];
            if (cur > 0) {
                acc += g_scores[b][prev][cur];
                cur = prev;
            } else {
                cur = 0;
            }
        }
        out[22016 + b] = acc;
    }
}

// ---------------- launch ----------------
extern "C" void kernel_launch(void* const* d_in, const int* in_sizes, int n_in,
                              void* d_out, int out_size)
{
    const float* x       = (const float*)d_in[0];
    const int*   lengths = (const int*)d_in[1];
    const float* wih0f = (const float*)d_in[2];
    const float* whh0f = (const float*)d_in[3];
    const float* bl0f  = (const float*)d_in[4];
    const float* wih0b = (const float*)d_in[5];
    const float* whh0b = (const float*)d_in[6];
    const float* bl0b  = (const float*)d_in[7];
    const float* wih1f = (const float*)d_in[8];
    const float* whh1f = (const float*)d_in[9];
    const float* bl1f  = (const float*)d_in[10];
    const float* wih1b = (const float*)d_in[11];
    const float* whh1b = (const float*)d_in[12];
    const float* bl1b  = (const float*)d_in[13];
    const float* a_s0 = (const float*)d_in[14];
    const float* w_s1 = (const float*)d_in[15];
    const float* b_s1 = (const float*)d_in[16];
    const float* a_s1 = (const float*)d_in[17];
    const float* w_s2 = (const float*)d_in[18];
    const float* b_s2 = (const float*)d_in[19];
    const float* a_c0 = (const float*)d_in[20];
    const float* w_c1 = (const float*)d_in[21];
    const float* b_c1 = (const float*)d_in[22];
    const float* a_c1 = (const float*)d_in[23];
    const float* w_c2 = (const float*)d_in[24];
    const float* b_c2 = (const float*)d_in[25];
    const float* a_b0 = (const float*)d_in[26];
    const float* w_b1 = (const float*)d_in[27];
    const float* b_b1 = (const float*)d_in[28];
    const float* a_b1 = (const float*)d_in[29];
    const float* w_b2 = (const float*)d_in[30];
    const float* b_b2 = (const float*)d_in[31];
    float* out = (float*)d_out;

    prep_k<<<512, 256>>>(wih0f, whh0f, wih0b, whh0b, wih1f, whh1f, wih1b, whh1b,
                         w_s1, w_c1, w_b1);

    inproj_k<INP><<<dim3(SS / 8, BB, 2), 512>>>(x, bl0f, bl0b, 0);
    recur_k<<<dim3(BB, 2), 256>>>(0);
    inproj_k<F2><<<dim3(SS / 8, BB, 2), 512>>>(x, bl1f, bl1b, 1);
    recur_k<<<dim3(BB, 2), 256>>>(1);

    cumsum_k<<<BB, F2>>>();
    determ_k<<<dim3(SS, BB), 128>>>(a_s0, b_s1);
    clsbin_k<<<dim3(SS, BB), 128>>>(a_c0, b_c1, a_c1, w_c2, b_c2,
                                    a_b0, b_b1, a_b1, w_b2, b_b2, out);
    scores_k<<<dim3(SS, BB), 256>>>(a_s0, a_s1, w_s2, b_s2);
    dp_k<<<BB, 64>>>();
    backtrack_k<<<1, 256>>>(lengths, out);
}